// round 12
// baseline (speedup 1.0000x reference)
#include <cuda_runtime.h>
#include <cstdint>

#define IDIM 128
#define HDIM 256
#define ODIM 16
#define MAXB 65536

// Static device scratch (no allocation allowed)
__device__ float g_w1f[HDIM * IDIM];                       // tanh(w1), [h][i]
__device__ unsigned long long g_w2p[HDIM * (ODIM / 2)];    // tanh(w2) packed f32x2 pairs, [h][opair]
__device__ unsigned g_masks[(size_t)HDIM * MAXB];          // 30-bit spike masks, [h][b]

// ---------------------------------------------------------------------------
// XLA EmitFastTanh with ptxas-fmad contraction (FFMA Horner chains), as the
// GPU reference's PTX would be compiled: clamp +-7.90531110763549805,
// |x|<0.0004 -> x, div.rn divide. Standalone muls stay FMUL.
// ---------------------------------------------------------------------------
__device__ __forceinline__ float xla_tanh(float x) {
    const float kClamp = 7.90531110763549805f;
    float ax = fabsf(x);
    float xc = fmaxf(-kClamp, fminf(kClamp, x));
    float x2 = __fmul_rn(xc, xc);
    float p = __fmaf_rn(x2, -2.76076847742355e-16f, 2.00018790482477e-13f);
    p = __fmaf_rn(x2, p, -8.60467152213735e-11f);
    p = __fmaf_rn(x2, p, 5.12229709037114e-08f);
    p = __fmaf_rn(x2, p, 1.48572235717979e-05f);
    p = __fmaf_rn(x2, p, 6.37261928875436e-04f);
    p = __fmaf_rn(x2, p, 4.89352455891786e-03f);
    float num = __fmul_rn(xc, p);
    float q = __fmaf_rn(x2, 1.19825839466702e-06f, 1.18534705686654e-04f);
    q = __fmaf_rn(x2, q, 2.26843463243900e-03f);
    q = __fmaf_rn(x2, q, 4.89352518554385e-03f);
    float r = __fdiv_rn(num, q);
    return (ax < 0.0004f) ? x : r;
}

// Leaky update, ptxas-contracted form: FFMA(beta, mem, c) then FSUB. (confirmed R11)
__device__ __forceinline__ float leaky_update(float mem, float c, float r) {
    return __fsub_rn(__fmaf_rn(0.95f, mem, c), r);
}

// Normalization: XLA algebraic simplifier rewrites x/3 -> x * (1/3). (confirmed R9)
__device__ __forceinline__ float norm_x(float v) {
    const float kRecip3 = 1.0f / 3.0f;   // 0x3EAAAAAB
    return __fmul_rn(fminf(3.0f, fmaxf(-3.0f, v)), kRecip3);
}

// ---------------------------------------------------------------------------
// Prep: tanh weights; pack w2 into output-pairs for f32x2 math
// ---------------------------------------------------------------------------
__global__ void prep_kernel(const float* __restrict__ w1, const float* __restrict__ w2) {
    int i = blockIdx.x * blockDim.x + threadIdx.x;
    if (i < HDIM * IDIM) {
        g_w1f[i] = xla_tanh(w1[i]);
    } else {
        int j = i - HDIM * IDIM;
        if (j < HDIM * (ODIM / 2)) {
            int h = j >> 3, op = j & 7;
            float lo = xla_tanh(w2[(2 * op) * HDIM + h]);
            float hi = xla_tanh(w2[(2 * op + 1) * HDIM + h]);
            unsigned long long v = ((unsigned long long)__float_as_uint(hi) << 32)
                                 | (unsigned long long)__float_as_uint(lo);
            g_w2p[j] = v;
        }
    }
}

// ---------------------------------------------------------------------------
// Phase 1: cur1 GEMM (serial ascending-k f32 fma, cuBLAS/Eigen order)
// + mem1 recursion -> 30-bit spike masks.
// ---------------------------------------------------------------------------
#define W1P 260
#define XP  129
#define P1_SMEM_BYTES ((128 * W1P + 64 * XP) * 4)   // 166144 B

__global__ void __launch_bounds__(256, 1) phase1_kernel(const float* __restrict__ x,
                                                        int B, int T) {
    extern __shared__ float sm[];
    float* w1s = sm;
    float* xs  = sm + 128 * W1P;
    int tid = threadIdx.x;
    int b0 = blockIdx.x * 64;

    // Load tanh(w1) transposed into smem
    for (int idx = tid; idx < (HDIM * IDIM) / 4; idx += 256) {
        int h = idx >> 5;
        int k4 = (idx & 31) << 2;
        float4 v = *(const float4*)&g_w1f[h * IDIM + k4];
        w1s[(k4 + 0) * W1P + h] = v.x;
        w1s[(k4 + 1) * W1P + h] = v.y;
        w1s[(k4 + 2) * W1P + h] = v.z;
        w1s[(k4 + 3) * W1P + h] = v.w;
    }
    // Load + normalize x tile: clip(x,-3,3) * (1/3)
    for (int idx = tid; idx < 64 * 32; idx += 256) {
        int s = idx >> 5;
        int k4 = (idx & 31) << 2;
        float4 v = make_float4(0.f, 0.f, 0.f, 0.f);
        if (b0 + s < B) v = *(const float4*)&x[(size_t)(b0 + s) * IDIM + k4];
        float* d = &xs[s * XP + k4];
        d[0] = norm_x(v.x);
        d[1] = norm_x(v.y);
        d[2] = norm_x(v.z);
        d[3] = norm_x(v.w);
    }
    __syncthreads();

    int tx = tid & 7;    // sample group: samples s = tx + 8*i
    int ty = tid >> 3;   // h group: h = ty*8 + j

    float acc[8][8];
#pragma unroll
    for (int i = 0; i < 8; ++i)
#pragma unroll
        for (int j = 0; j < 8; ++j) acc[i][j] = 0.0f;

#pragma unroll 2
    for (int k = 0; k < IDIM; ++k) {
        float a[8];
#pragma unroll
        for (int i = 0; i < 8; ++i) a[i] = xs[(tx + 8 * i) * XP + k];
        float4 bv0 = *(const float4*)&w1s[k * W1P + ty * 8];
        float4 bv1 = *(const float4*)&w1s[k * W1P + ty * 8 + 4];
        float bb[8] = {bv0.x, bv0.y, bv0.z, bv0.w, bv1.x, bv1.y, bv1.z, bv1.w};
#pragma unroll
        for (int i = 0; i < 8; ++i)
#pragma unroll
            for (int j = 0; j < 8; ++j)
                acc[i][j] = fmaf(a[i], bb[j], acc[i][j]);
    }

    // mem1 recursion -> 1 bit per step, store mask
#pragma unroll
    for (int i = 0; i < 8; ++i) {
        int b = b0 + tx + 8 * i;
#pragma unroll
        for (int j = 0; j < 8; ++j) {
            float c = acc[i][j];
            float mem = 0.0f;
            unsigned msk = 0u;
            for (int t = 0; t < T; ++t) {
                float r = (mem > 1.0f) ? 1.0f : 0.0f;
                mem = leaky_update(mem, c, r);
                msk |= (mem > 1.0f ? 1u : 0u) << t;
            }
            if (b < B) {
                int h = ty * 8 + j;
                g_masks[(size_t)h * B + b] = msk;
            }
        }
    }
}

// ---------------------------------------------------------------------------
// Phase 2: cur2 via mask-selected f32x2 fma (ascending h — exact vs fadd since
// spikes are exactly 0/1), mem2 recursion, spike output.
// ---------------------------------------------------------------------------
__device__ __forceinline__ void fma2(unsigned long long& d, unsigned long long a,
                                     unsigned long long b) {
    asm("fma.rn.f32x2 %0, %1, %2, %0;" : "+l"(d) : "l"(a), "l"(b));
}

__device__ __forceinline__ float2 unpack2(unsigned long long v) {
    float2 r;
    asm("mov.b64 {%0, %1}, %2;" : "=f"(r.x), "=f"(r.y) : "l"(v));
    return r;
}

__global__ void __launch_bounds__(128) phase2_kernel(int T, int B, float* __restrict__ out) {
    __shared__ unsigned long long w2s[HDIM * 8];
    int tid = threadIdx.x;
    for (int i = tid; i < HDIM * 8; i += 128) w2s[i] = g_w2p[i];
    __syncthreads();

    int b = blockIdx.x * 128 + tid;
    if (b >= B) return;

    float mem2[ODIM];
#pragma unroll
    for (int o = 0; o < ODIM; ++o) mem2[o] = 0.0f;

    int NG = (T + 4) / 5;
    for (int g = 0; g < NG; ++g) {
        unsigned long long acc[5][8];
#pragma unroll
        for (int t = 0; t < 5; ++t)
#pragma unroll
            for (int op = 0; op < 8; ++op) acc[t][op] = 0ull;

        int shift = g * 5;
        const unsigned* mp = g_masks + b;
        for (int h = 0; h < HDIM; ++h) {
            unsigned m = (*mp) >> shift;
            mp += B;
            unsigned long long w[8];
#pragma unroll
            for (int op = 0; op < 8; ++op) w[op] = w2s[h * 8 + op];
#pragma unroll
            for (int t = 0; t < 5; ++t) {
                unsigned long long sp = ((m >> t) & 1u) ? 0x3f8000003f800000ULL : 0ull;
#pragma unroll
                for (int op = 0; op < 8; ++op) fma2(acc[t][op], w[op], sp);
            }
        }

        // mem2 recursion + output for the 5 steps of this pass
#pragma unroll
        for (int tt = 0; tt < 5; ++tt) {
            int t = g * 5 + tt;
            if (t >= T) break;
            float4 o4[4];
            float* ov = (float*)o4;
#pragma unroll
            for (int op = 0; op < 8; ++op) {
                float2 c = unpack2(acc[tt][op]);
                int o0 = 2 * op;
                float r0 = (mem2[o0] > 1.0f) ? 1.0f : 0.0f;
                mem2[o0] = leaky_update(mem2[o0], c.x, r0);
                ov[o0] = (mem2[o0] > 1.0f) ? 1.0f : 0.0f;
                float r1 = (mem2[o0 + 1] > 1.0f) ? 1.0f : 0.0f;
                mem2[o0 + 1] = leaky_update(mem2[o0 + 1], c.y, r1);
                ov[o0 + 1] = (mem2[o0 + 1] > 1.0f) ? 1.0f : 0.0f;
            }
            float4* dst = (float4*)(out + ((size_t)t * B + b) * ODIM);
            dst[0] = o4[0];
            dst[1] = o4[1];
            dst[2] = o4[2];
            dst[3] = o4[3];
        }
    }
}

// ---------------------------------------------------------------------------
// Launch
// ---------------------------------------------------------------------------
extern "C" void kernel_launch(void* const* d_in, const int* in_sizes, int n_in,
                              void* d_out, int out_size) {
    if (n_in < 3) return;
    const float* x  = (const float*)d_in[0];
    const float* w1 = (const float*)d_in[1];
    const float* w2 = (const float*)d_in[2];

    int B = in_sizes[0] / IDIM;
    if (B > MAXB) B = MAXB;
    int T = out_size / (B * ODIM);
    if (T > 32) T = 32;
    if (T < 1) T = 1;

    int prep_elems = HDIM * IDIM + HDIM * (ODIM / 2);
    prep_kernel<<<(prep_elems + 255) / 256, 256>>>(w1, w2);

    cudaFuncSetAttribute(phase1_kernel, cudaFuncAttributeMaxDynamicSharedMemorySize,
                         P1_SMEM_BYTES);
    phase1_kernel<<<(B + 63) / 64, 256, P1_SMEM_BYTES>>>(x, B, T);

    phase2_kernel<<<(B + 127) / 128, 128>>>(T, B, (float*)d_out);
}

// round 13
// speedup vs baseline: 1.0328x; 1.0328x over previous
#include <cuda_runtime.h>
#include <cstdint>

#define IDIM 128
#define HDIM 256
#define ODIM 16
#define MAXB 65536

// Static device scratch (no allocation allowed).
// g_masks padded by one h-row so phase2's unconditional prefetch never reads OOB.
__device__ unsigned g_masks[(size_t)(HDIM + 1) * MAXB];    // 30-bit spike masks, [h][b]

// ---------------------------------------------------------------------------
// XLA EmitFastTanh, ptxas-contracted form (FFMA Horner chains) — confirmed
// bit-exact vs reference in R12. clamp +-7.90531110763549805, |x|<0.0004 -> x.
// ---------------------------------------------------------------------------
__device__ __forceinline__ float xla_tanh(float x) {
    const float kClamp = 7.90531110763549805f;
    float ax = fabsf(x);
    float xc = fmaxf(-kClamp, fminf(kClamp, x));
    float x2 = __fmul_rn(xc, xc);
    float p = __fmaf_rn(x2, -2.76076847742355e-16f, 2.00018790482477e-13f);
    p = __fmaf_rn(x2, p, -8.60467152213735e-11f);
    p = __fmaf_rn(x2, p, 5.12229709037114e-08f);
    p = __fmaf_rn(x2, p, 1.48572235717979e-05f);
    p = __fmaf_rn(x2, p, 6.37261928875436e-04f);
    p = __fmaf_rn(x2, p, 4.89352455891786e-03f);
    float num = __fmul_rn(xc, p);
    float q = __fmaf_rn(x2, 1.19825839466702e-06f, 1.18534705686654e-04f);
    q = __fmaf_rn(x2, q, 2.26843463243900e-03f);
    q = __fmaf_rn(x2, q, 4.89352518554385e-03f);
    float r = __fdiv_rn(num, q);
    return (ax < 0.0004f) ? x : r;
}

// Leaky update, confirmed form: FFMA(beta, mem, c) then FSUB.
__device__ __forceinline__ float leaky_update(float mem, float c, float r) {
    return __fsub_rn(__fmaf_rn(0.95f, mem, c), r);
}

// Normalization, confirmed: clip then multiply by (1/3).
__device__ __forceinline__ float norm_x(float v) {
    const float kRecip3 = 1.0f / 3.0f;   // 0x3EAAAAAB
    return __fmul_rn(fminf(3.0f, fmaxf(-3.0f, v)), kRecip3);
}

// Packed f32x2 helpers (per-lane ops — bit-identical to scalar)
__device__ __forceinline__ void fma2(unsigned long long& d, unsigned long long a,
                                     unsigned long long b) {
    asm("fma.rn.f32x2 %0, %1, %2, %0;" : "+l"(d) : "l"(a), "l"(b));
}
__device__ __forceinline__ unsigned long long dup2(float a) {
    unsigned long long r;
    asm("mov.b64 %0, {%1, %1};" : "=l"(r) : "f"(a));
    return r;
}
__device__ __forceinline__ float2 unpack2(unsigned long long v) {
    float2 r;
    asm("mov.b64 {%0, %1}, %2;" : "=f"(r.x), "=f"(r.y) : "l"(v));
    return r;
}

// ---------------------------------------------------------------------------
// Phase 1: inline tanh(w1) -> smem (transposed), cur1 GEMM with f32x2 h-pair
// packing (exact: per-lane ascending-k fma), mem1 recursion -> spike masks.
// CTA: 256 thr, 64 samples x 256 h, register tile 8 samples x 4 h-pairs.
// ---------------------------------------------------------------------------
#define W1P 260
#define XP  129
#define P1_SMEM_BYTES ((128 * W1P + 64 * XP) * 4)   // 166144 B

__global__ void __launch_bounds__(256, 1) phase1_kernel(const float* __restrict__ x,
                                                        const float* __restrict__ w1,
                                                        int B, int T) {
    extern __shared__ float sm[];
    float* w1s = sm;                    // [k][h], pitch W1P
    float* xs  = sm + 128 * W1P;        // [s][k], pitch XP
    int tid = threadIdx.x;
    int b0 = blockIdx.x * 64;

    // tanh(w1) transposed into smem (each block computes identically — deterministic)
    for (int idx = tid; idx < (HDIM * IDIM) / 4; idx += 256) {
        int h = idx >> 5;
        int k4 = (idx & 31) << 2;
        float4 v = *(const float4*)&w1[h * IDIM + k4];
        w1s[(k4 + 0) * W1P + h] = xla_tanh(v.x);
        w1s[(k4 + 1) * W1P + h] = xla_tanh(v.y);
        w1s[(k4 + 2) * W1P + h] = xla_tanh(v.z);
        w1s[(k4 + 3) * W1P + h] = xla_tanh(v.w);
    }
    // Load + normalize x tile
    for (int idx = tid; idx < 64 * 32; idx += 256) {
        int s = idx >> 5;
        int k4 = (idx & 31) << 2;
        float4 v = make_float4(0.f, 0.f, 0.f, 0.f);
        if (b0 + s < B) v = *(const float4*)&x[(size_t)(b0 + s) * IDIM + k4];
        float* d = &xs[s * XP + k4];
        d[0] = norm_x(v.x);
        d[1] = norm_x(v.y);
        d[2] = norm_x(v.z);
        d[3] = norm_x(v.w);
    }
    __syncthreads();

    int tx = tid & 7;    // sample group: samples s = tx + 8*i
    int ty = tid >> 3;   // h group: h = ty*8 + {0..7} as 4 pairs

    unsigned long long acc2[8][4];
#pragma unroll
    for (int i = 0; i < 8; ++i)
#pragma unroll
        for (int jp = 0; jp < 4; ++jp) acc2[i][jp] = 0ull;

#pragma unroll 2
    for (int k = 0; k < IDIM; ++k) {
        unsigned long long ad[8];
#pragma unroll
        for (int i = 0; i < 8; ++i) ad[i] = dup2(xs[(tx + 8 * i) * XP + k]);
        // b pairs: 8 consecutive h floats = 2x 16B loads = 4 64-bit pairs (16B aligned)
        const ulonglong2* bp = (const ulonglong2*)&w1s[k * W1P + ty * 8];
        ulonglong2 bv0 = bp[0];
        ulonglong2 bv1 = bp[1];
        unsigned long long bb[4] = {bv0.x, bv0.y, bv1.x, bv1.y};
#pragma unroll
        for (int i = 0; i < 8; ++i)
#pragma unroll
            for (int jp = 0; jp < 4; ++jp)
                fma2(acc2[i][jp], ad[i], bb[jp]);
    }

    // mem1 recursion (4-instr predicated form; value-identical to fsub(fma, r))
#pragma unroll
    for (int i = 0; i < 8; ++i) {
        int b = b0 + tx + 8 * i;
#pragma unroll
        for (int jp = 0; jp < 4; ++jp) {
            float2 cc = unpack2(acc2[i][jp]);
#pragma unroll
            for (int half = 0; half < 2; ++half) {
                float c = half ? cc.y : cc.x;
                float mem = 0.0f;
                unsigned msk = 0u;
                bool p = false;
                for (int t = 0; t < T; ++t) {
                    mem = __fmaf_rn(0.95f, mem, c);
                    if (p) mem = __fsub_rn(mem, 1.0f);
                    p = (mem > 1.0f);
                    if (p) msk |= 1u << t;
                }
                if (b < B) {
                    int h = ty * 8 + 2 * jp + half;
                    g_masks[(size_t)h * B + b] = msk;
                }
            }
        }
    }
}

// ---------------------------------------------------------------------------
// Phase 2: inline tanh(w2) -> smem pairs; cur2 via mask-selected f32x2 fma
// (ascending h, exact); 5 passes of 6 steps; next-h mask prefetch;
// mem2 recursion (confirmed form), spike output.
// ---------------------------------------------------------------------------
__global__ void __launch_bounds__(128) phase2_kernel(const float* __restrict__ w2,
                                                     int T, int B,
                                                     float* __restrict__ out) {
    __shared__ unsigned long long w2s[HDIM * 8];
    int tid = threadIdx.x;
    // tanh(w2) packed into output-pairs (each block computes identically)
    for (int j = tid; j < HDIM * 8; j += 128) {
        int h = j >> 3, op = j & 7;
        float lo = xla_tanh(w2[(2 * op) * HDIM + h]);
        float hi = xla_tanh(w2[(2 * op + 1) * HDIM + h]);
        w2s[j] = ((unsigned long long)__float_as_uint(hi) << 32)
               | (unsigned long long)__float_as_uint(lo);
    }
    __syncthreads();

    int b = blockIdx.x * 128 + tid;
    if (b >= B) return;

    float mem2[ODIM];
#pragma unroll
    for (int o = 0; o < ODIM; ++o) mem2[o] = 0.0f;

    int NG = (T + 5) / 6;
    for (int g = 0; g < NG; ++g) {
        unsigned long long acc[6][8];
#pragma unroll
        for (int t = 0; t < 6; ++t)
#pragma unroll
            for (int op = 0; op < 8; ++op) acc[t][op] = 0ull;

        int shift = g * 6;
        const unsigned* mp = g_masks + b;
        unsigned m = (*mp) >> shift;
        mp += B;
        for (int h = 0; h < HDIM; ++h) {
            unsigned mn = (*mp) >> shift;   // prefetch next h (padded row at h=255)
            mp += B;
            unsigned long long w[8];
#pragma unroll
            for (int op = 0; op < 8; ++op) w[op] = w2s[h * 8 + op];
#pragma unroll
            for (int t = 0; t < 6; ++t) {
                unsigned long long sp = ((m >> t) & 1u) ? 0x3f8000003f800000ULL : 0ull;
#pragma unroll
                for (int op = 0; op < 8; ++op) fma2(acc[t][op], w[op], sp);
            }
            m = mn;
        }

        // mem2 recursion + output for the 6 steps of this pass
#pragma unroll
        for (int tt = 0; tt < 6; ++tt) {
            int t = g * 6 + tt;
            if (t >= T) break;
            float4 o4[4];
            float* ov = (float*)o4;
#pragma unroll
            for (int op = 0; op < 8; ++op) {
                float2 c = unpack2(acc[tt][op]);
                int o0 = 2 * op;
                float r0 = (mem2[o0] > 1.0f) ? 1.0f : 0.0f;
                mem2[o0] = leaky_update(mem2[o0], c.x, r0);
                ov[o0] = (mem2[o0] > 1.0f) ? 1.0f : 0.0f;
                float r1 = (mem2[o0 + 1] > 1.0f) ? 1.0f : 0.0f;
                mem2[o0 + 1] = leaky_update(mem2[o0 + 1], c.y, r1);
                ov[o0 + 1] = (mem2[o0 + 1] > 1.0f) ? 1.0f : 0.0f;
            }
            float4* dst = (float4*)(out + ((size_t)t * B + b) * ODIM);
            dst[0] = o4[0];
            dst[1] = o4[1];
            dst[2] = o4[2];
            dst[3] = o4[3];
        }
    }
}

// ---------------------------------------------------------------------------
// Launch (2 kernels per call so ncu -s 5 -c 1 lands on a hot kernel)
// ---------------------------------------------------------------------------
extern "C" void kernel_launch(void* const* d_in, const int* in_sizes, int n_in,
                              void* d_out, int out_size) {
    if (n_in < 3) return;
    const float* x  = (const float*)d_in[0];
    const float* w1 = (const float*)d_in[1];
    const float* w2 = (const float*)d_in[2];

    int B = in_sizes[0] / IDIM;
    if (B > MAXB) B = MAXB;
    int T = out_size / (B * ODIM);
    if (T > 32) T = 32;
    if (T < 1) T = 1;

    cudaFuncSetAttribute(phase1_kernel, cudaFuncAttributeMaxDynamicSharedMemorySize,
                         P1_SMEM_BYTES);
    phase1_kernel<<<(B + 63) / 64, 256, P1_SMEM_BYTES>>>(x, w1, B, T);

    phase2_kernel<<<(B + 127) / 128, 128>>>(w2, T, B, (float*)d_out);
}